// round 2
// baseline (speedup 1.0000x reference)
#include <cuda_runtime.h>
#include <cstdint>

#define NSTATES 35
#define SPAD    40
#define NB      64
#define TT      512
#define DDIM    2496
#define BTROWS  (NB * TT)   // 32768

// Scratch (no cudaMalloc allowed)
__device__ float g_w[(size_t)BTROWS * NSTATES];  // exp((m_sq - 2 x.m)/-500), ~4.6 MB
__device__ float g_msq[SPAD];                    // |m_s|^2 (padded with 0)
__device__ float g_xoff[NB];                     // sum_t |x_bt|^2 / (-500)

// ---------------------------------------------------------------------------
// Kernel 0: m_sq per state + zero the per-batch offsets (fresh every replay)
// ---------------------------------------------------------------------------
__global__ void k_prep(const float* __restrict__ m) {
    __shared__ float sm[256];
    int s = blockIdx.x;
    float acc = 0.f;
    if (s < NSTATES) {
        const float* row = m + (size_t)s * DDIM;
        for (int k = threadIdx.x; k < DDIM; k += 256) {
            float v = row[k];
            acc = fmaf(v, v, acc);
        }
    }
    sm[threadIdx.x] = acc;
    __syncthreads();
    for (int off = 128; off > 0; off >>= 1) {
        if (threadIdx.x < (unsigned)off) sm[threadIdx.x] += sm[threadIdx.x + off];
        __syncthreads();
    }
    if (threadIdx.x == 0) g_msq[s] = sm[0];
    if (blockIdx.x == 0 && threadIdx.x < NB) g_xoff[threadIdx.x] = 0.f;
}

// ---------------------------------------------------------------------------
// Kernel 1: tf32 warp-MMA GEMM  w[bt][s] = exp((m_sq[s] - 2*x.m)/-500)
//           + exact fp32 |x|^2 accumulation into g_xoff
// Each warp: 64 rows (4 m-tiles of m16), 40 cols (5 n-tiles of n8), K=2496.
// k within each k8 chunk is permuted so every thread loads contiguous float2
// (permutation applied consistently to A and B slots -> same dot product).
// ---------------------------------------------------------------------------
#define MT  4
#define NTL 5

__device__ __forceinline__ void mma_tf32(float* d,
    uint32_t a0, uint32_t a1, uint32_t a2, uint32_t a3,
    uint32_t b0, uint32_t b1) {
    asm volatile(
        "mma.sync.aligned.m16n8k8.row.col.f32.tf32.tf32.f32 "
        "{%0,%1,%2,%3}, {%4,%5,%6,%7}, {%8,%9}, {%0,%1,%2,%3};\n"
        : "+f"(d[0]), "+f"(d[1]), "+f"(d[2]), "+f"(d[3])
        : "r"(a0), "r"(a1), "r"(a2), "r"(a3), "r"(b0), "r"(b1));
}

__global__ void __launch_bounds__(64) k_gemm(const float* __restrict__ x,
                                             const float* __restrict__ mM) {
    const int warp = blockIdx.x * 2 + (threadIdx.x >> 5);
    const int lane = threadIdx.x & 31;
    const int g = lane >> 2;        // 0..7
    const int c = lane & 3;         // 0..3
    const int row0 = warp * (MT * 16);

    const float* pa[MT][2];
#pragma unroll
    for (int mt = 0; mt < MT; mt++) {
        pa[mt][0] = x + (size_t)(row0 + mt * 16 + g)     * DDIM + 2 * c;
        pa[mt][1] = x + (size_t)(row0 + mt * 16 + g + 8) * DDIM + 2 * c;
    }
    const float* pb[NTL];
    bool bvalid[NTL];
#pragma unroll
    for (int nt = 0; nt < NTL; nt++) {
        int s = nt * 8 + g;
        bvalid[nt] = (s < NSTATES);
        int sc = s < NSTATES ? s : (NSTATES - 1);
        pb[nt] = mM + (size_t)sc * DDIM + 2 * c;
    }

    float acc[MT][NTL][4];
#pragma unroll
    for (int mt = 0; mt < MT; mt++)
#pragma unroll
        for (int nt = 0; nt < NTL; nt++)
#pragma unroll
            for (int i = 0; i < 4; i++) acc[mt][nt][i] = 0.f;

    float xsq[MT][2];
#pragma unroll
    for (int mt = 0; mt < MT; mt++) { xsq[mt][0] = 0.f; xsq[mt][1] = 0.f; }

#pragma unroll 2
    for (int kk = 0; kk < DDIM; kk += 8) {
        float2 alo[MT], ahi[MT];
#pragma unroll
        for (int mt = 0; mt < MT; mt++) {
            alo[mt] = *(const float2*)(pa[mt][0] + kk);
            ahi[mt] = *(const float2*)(pa[mt][1] + kk);
        }
        float2 bv[NTL];
#pragma unroll
        for (int nt = 0; nt < NTL; nt++) {
            float2 t = *(const float2*)(pb[nt] + kk);
            bv[nt].x = bvalid[nt] ? t.x : 0.f;
            bv[nt].y = bvalid[nt] ? t.y : 0.f;
        }
#pragma unroll
        for (int mt = 0; mt < MT; mt++) {
            xsq[mt][0] = fmaf(alo[mt].x, alo[mt].x, xsq[mt][0]);
            xsq[mt][0] = fmaf(alo[mt].y, alo[mt].y, xsq[mt][0]);
            xsq[mt][1] = fmaf(ahi[mt].x, ahi[mt].x, xsq[mt][1]);
            xsq[mt][1] = fmaf(ahi[mt].y, ahi[mt].y, xsq[mt][1]);
#pragma unroll
            for (int nt = 0; nt < NTL; nt++) {
                mma_tf32(acc[mt][nt],
                         __float_as_uint(alo[mt].x), __float_as_uint(ahi[mt].x),
                         __float_as_uint(alo[mt].y), __float_as_uint(ahi[mt].y),
                         __float_as_uint(bv[nt].x),  __float_as_uint(bv[nt].y));
            }
        }
    }

    // Epilogue: w = exp((m_sq - 2*xm) * (-1/500)), stored row-major [bt][35]
    const float NEG_INV = -1.0f / 500.0f;
#pragma unroll
    for (int mt = 0; mt < MT; mt++) {
#pragma unroll
        for (int h = 0; h < 2; h++) {
            int row = row0 + mt * 16 + g + h * 8;
#pragma unroll
            for (int nt = 0; nt < NTL; nt++) {
                int col = nt * 8 + 2 * c;
                float v0 = acc[mt][nt][2 * h + 0];
                float v1 = acc[mt][nt][2 * h + 1];
                float w0 = __expf((g_msq[col]     - 2.f * v0) * NEG_INV);
                float w1 = __expf((g_msq[col + 1] - 2.f * v1) * NEG_INV);
                if (col < NSTATES)
                    g_w[(size_t)row * NSTATES + col] = w0;
                if (col + 1 < NSTATES)
                    g_w[(size_t)row * NSTATES + col + 1] = w1;
            }
        }
    }

    // |x|^2 contribution: warp covers 64 rows, all within one batch b=row0>>9.
    float tot = 0.f;
#pragma unroll
    for (int mt = 0; mt < MT; mt++) tot += xsq[mt][0] + xsq[mt][1];
    tot += __shfl_xor_sync(0xffffffffu, tot, 16);
    tot += __shfl_xor_sync(0xffffffffu, tot, 8);
    tot += __shfl_xor_sync(0xffffffffu, tot, 4);
    tot += __shfl_xor_sync(0xffffffffu, tot, 2);
    tot += __shfl_xor_sync(0xffffffffu, tot, 1);
    if (lane == 0) atomicAdd(&g_xoff[row0 >> 9], tot * NEG_INV);
}

// ---------------------------------------------------------------------------
// Kernel 2: linear-domain forward recursion. One warp per batch.
// T[i][j]: 0.1 (j=i), 0.8 (j=i+1 mod 35), 0.08 (j=i+2 mod 35), +0.02/35 all.
// s_j = eps*S + 0.1 p_j + 0.8 p_{j-1} + 0.08 p_{j-2};  p'_j = w_j * s_j.
// Lanes 0..31 hold states 0..31 (p); lanes 0..2 also hold 32..34 (q).
// Renormalize by 1/S every 16 steps; accumulate log scale in Cacc.
// ---------------------------------------------------------------------------
struct FwdLane {
    int i1, i2, iF;
    bool is0, lt2, lt3;
};

__device__ __forceinline__ float fwd_step(float& p, float& q, float wp, float wq,
                                          const FwdLane& L) {
    const unsigned FULL = 0xffffffffu;
    const float EPS = 0.02f / 35.0f;
    float v = p + (L.lt3 ? q : 0.0f);
    float S = v;
    S += __shfl_xor_sync(FULL, S, 16);
    S += __shfl_xor_sync(FULL, S, 8);
    S += __shfl_xor_sync(FULL, S, 4);
    S += __shfl_xor_sync(FULL, S, 2);
    S += __shfl_xor_sync(FULL, S, 1);
    float A1 = __shfl_up_sync(FULL, p, 1);     // p[l-1]
    float A2 = __shfl_up_sync(FULL, p, 2);     // p[l-2]
    float Cr = __shfl_sync(FULL, q, L.i1);     // lane0->q2, lane1->q0, lane2->q1
    float Dr = __shfl_sync(FULL, q, L.i2);     // lane0->q1, lane1->q2, lane2->q0
    float Fv = __shfl_sync(FULL, p, L.iF);     // lane0->p30, lane1->p31
    float Gv = __shfl_sync(FULL, p, 31);       // p31
    float pm1 = L.is0 ? Cr : A1;   // state j-1 (j=lane)
    float pm2 = L.lt2 ? Dr : A2;   // state j-2
    float qm1 = L.is0 ? Gv : Cr;   // state (32+l)-1
    float qm2 = L.lt2 ? Fv : Dr;   // state (32+l)-2
    float base = EPS * S;
    float sp = fmaf(0.1f, p, fmaf(0.8f, pm1, fmaf(0.08f, pm2, base)));
    float sq = fmaf(0.1f, q, fmaf(0.8f, qm1, fmaf(0.08f, qm2, base)));
    p = wp * sp;
    q = L.lt3 ? (wq * sq) : 0.0f;
    return S;   // sum of PRE-update p (used for renorm)
}

__global__ void __launch_bounds__(32) k_fwd(float* __restrict__ out) {
    const int b = blockIdx.x;
    const int l = threadIdx.x;
    const float* wb = g_w + (size_t)b * TT * NSTATES;
    const unsigned FULL = 0xffffffffu;

    FwdLane L;
    L.i1 = (l + 2) % 3;
    L.i2 = (l + 1) % 3;
    L.iF = (30 + l) & 31;
    L.is0 = (l == 0);
    L.lt2 = (l < 2);
    L.lt3 = (l < 3);

    // t = 0: alpha0 = emis0 + prior; prior = +10 (s=0), -10 else; shift by 10.
    const float EXPM20 = 2.0611536e-09f;
    float p = wb[l] * (L.is0 ? 1.0f : EXPM20);
    float q = L.lt3 ? (wb[32 + l] * EXPM20) : 0.0f;
    float Cacc = 10.0f;

    // prefetch ring (depth 4) for w
    float bufp[4], bufq[4];
#pragma unroll
    for (int d = 0; d < 4; d++) {
        int t = 1 + d;
        bufp[d] = __ldg(wb + t * NSTATES + l);
        bufq[d] = L.lt3 ? __ldg(wb + t * NSTATES + 32 + l) : 0.0f;
    }

    int t = 1;
    for (int it = 0; it < 127; it++) {        // 127*4 = 508 steps: t = 1..508
#pragma unroll
        for (int u = 0; u < 4; u++) {
            float S = fwd_step(p, q, bufp[u], bufq[u], L);
            int tn = t + 4;
            if (tn < TT) {
                bufp[u] = __ldg(wb + tn * NSTATES + l);
                bufq[u] = L.lt3 ? __ldg(wb + tn * NSTATES + 32 + l) : 0.0f;
            }
            if ((t & 15) == 0) {
                float rs = __fdividef(1.0f, S);
                Cacc += __logf(S);
                p *= rs;
                q *= rs;
            }
            t++;
        }
    }
#pragma unroll
    for (int u = 0; u < 3; u++) {             // t = 509, 510, 511
        fwd_step(p, q, bufp[u], bufq[u], L);
        t++;
    }

    float v = p + (L.lt3 ? q : 0.0f);
    v += __shfl_xor_sync(FULL, v, 16);
    v += __shfl_xor_sync(FULL, v, 8);
    v += __shfl_xor_sync(FULL, v, 4);
    v += __shfl_xor_sync(FULL, v, 2);
    v += __shfl_xor_sync(FULL, v, 1);
    if (l == 0) out[b] = __logf(v) + Cacc + g_xoff[b];
}

// ---------------------------------------------------------------------------
extern "C" void kernel_launch(void* const* d_in, const int* in_sizes, int n_in,
                              void* d_out, int out_size) {
    const float* obs = (const float*)d_in[0];  // [64,512,16,13,12]
    const float* m   = (const float*)d_in[1];  // [35,16,13,12]
    float* out = (float*)d_out;                // [64]

    k_prep<<<SPAD, 256>>>(m);
    k_gemm<<<BTROWS / 128, 64>>>(obs, m);      // 256 CTAs x 2 warps x 64 rows
    k_fwd<<<NB, 32>>>(out);
}